// round 17
// baseline (speedup 1.0000x reference)
#include <cuda_runtime.h>

#define Bsz 32
#define Hh 480
#define Ww 640
#define HW (Hh*Ww)          // 307200 pixels per channel-plane
#define HW8 (HW/8)          // 38400 8-float groups per plane
#define TPB 256
#define PBLK (HW8/TPB)      // 150 blocks per image
#define IMG_PER_G 4
#define NGRP (Bsz/IMG_PER_G)   // 8 groups

__device__ float d_part[Bsz * PBLK];   // per-block partial gray sums

__device__ __forceinline__ float clip01(float v) {
    return fminf(fmaxf(v, 0.0f), 1.0f);
}

__device__ __forceinline__ float rcp_approx(float x) {
    float r;
    asm("rcp.approx.f32 %0, %1;" : "=f"(r) : "f"(x));
    return r;
}

struct f8 { float v[8]; };

__device__ __forceinline__ void unpack2(unsigned long long u, float& a, float& b) {
    asm("mov.b64 {%0,%1}, %2;" : "=f"(a), "=f"(b) : "l"(u));
}
__device__ __forceinline__ unsigned long long pack2(float a, float b) {
    unsigned long long u;
    asm("mov.b64 %0, {%1,%2};" : "=l"(u) : "f"(a), "f"(b));
    return u;
}

__device__ __forceinline__ f8 ld8(const float* p) {
    unsigned long long x0, x1, x2, x3;
    asm("ld.global.nc.v4.b64 {%0,%1,%2,%3}, [%4];"
        : "=l"(x0), "=l"(x1), "=l"(x2), "=l"(x3) : "l"(p));
    f8 r;
    unpack2(x0, r.v[0], r.v[1]); unpack2(x1, r.v[2], r.v[3]);
    unpack2(x2, r.v[4], r.v[5]); unpack2(x3, r.v[6], r.v[7]);
    return r;
}

__device__ __forceinline__ void st8_cs(float* p, const float* s) {
    unsigned long long x0 = pack2(s[0], s[1]);
    unsigned long long x1 = pack2(s[2], s[3]);
    unsigned long long x2 = pack2(s[4], s[5]);
    unsigned long long x3 = pack2(s[6], s[7]);
    asm volatile("st.global.cs.v4.b64 [%0], {%1,%2,%3,%4};"
                 :: "l"(p), "l"(x0), "l"(x1), "l"(x2), "l"(x3) : "memory");
}

// Reduce one GROUP of 4 images.  grid = (PBLK, IMG_PER_G)
__global__ void __launch_bounds__(TPB) gray_reduce_g(const float* __restrict__ x,
                                                     const float* __restrict__ bf,
                                                     int g0) {
    const int b    = g0 + blockIdx.y;
    const int slot = blockIdx.x;
    const int g8   = slot * TPB + threadIdx.x;
    const float s  = bf[b];

    const float* base = x + (size_t)b * 3 * HW + (size_t)g8 * 8;
    f8 R  = ld8(base);
    f8 G  = ld8(base + HW);
    f8 Bv = ld8(base + 2 * HW);

    float acc = 0.0f;
    #pragma unroll
    for (int k = 0; k < 8; k++) {
        float r = clip01(R.v[k] * s), g = clip01(G.v[k] * s), bb = clip01(Bv.v[k] * s);
        acc += 0.299f * r + 0.587f * g + 0.114f * bb;
    }

    for (int off = 16; off > 0; off >>= 1)
        acc += __shfl_down_sync(0xFFFFFFFF, acc, off);

    __shared__ float warp_part[TPB / 32];
    const int lane = threadIdx.x & 31;
    const int wid  = threadIdx.x >> 5;
    if (lane == 0) warp_part[wid] = acc;
    __syncthreads();
    if (wid == 0) {
        float v = (lane < TPB / 32) ? warp_part[lane] : 0.0f;
        for (int off = 4; off > 0; off >>= 1)
            v += __shfl_down_sync(0xFFFFFFFF, v, off);
        if (lane == 0) d_part[b * PBLK + slot] = v;
    }
}

__device__ __forceinline__ float fracf(float x) { return x - floorf(x); }

__device__ __forceinline__ float hsv_ch(float u, float cr, float minc) {
    float t = fracf(u);
    float a = fabsf(fmaf(t, 6.0f, -3.0f)) - 1.0f;
    float w = fminf(fmaxf(a, 0.0f), 1.0f);
    return fmaf(cr, w, minc);
}

// Transform one GROUP of 4 images.  grid = PBLK*IMG_PER_G blocks.
__global__ void __launch_bounds__(TPB) color_xform_g(const float* __restrict__ x,
                            const float* __restrict__ bfv,
                            const float* __restrict__ cfv,
                            const float* __restrict__ sfv,
                            const float* __restrict__ hfv,
                            float* __restrict__ out,
                            int g0) {
    const int blk  = blockIdx.x;
    const int b    = g0 + blk / PBLK;
    const int slot = blk % PBLK;
    const int g8   = slot * TPB + threadIdx.x;

    const float* ibase = x   + (size_t)b * 3 * HW + (size_t)g8 * 8;
    float*       obase = out + (size_t)b * 3 * HW + (size_t)g8 * 8;

    // Long-latency pixel loads first (overlap with partial re-reduction).
    f8 R  = ld8(ibase);
    f8 G  = ld8(ibase + HW);
    f8 Bv = ld8(ibase + 2 * HW);

    // Re-reduce the 150 per-block partials for this image (L2-hot, deterministic).
    const int t = threadIdx.x;
    float acc = (t < PBLK) ? d_part[b * PBLK + t] : 0.0f;
    for (int off = 16; off > 0; off >>= 1)
        acc += __shfl_down_sync(0xFFFFFFFF, acc, off);
    __shared__ float warp_part[TPB / 32];
    __shared__ float s_mean;
    const int lane = t & 31;
    const int wid  = t >> 5;
    if (lane == 0) warp_part[wid] = acc;
    __syncthreads();
    if (wid == 0) {
        float v = (lane < TPB / 32) ? warp_part[lane] : 0.0f;
        for (int off = 4; off > 0; off >>= 1)
            v += __shfl_down_sync(0xFFFFFFFF, v, off);
        if (lane == 0) s_mean = v * (1.0f / (float)HW);
    }
    __syncthreads();
    const float mean = s_mean;

    const float bf = bfv[b];
    const float cf = cfv[b];
    const float sf = sfv[b];
    const float hf = hfv[b];
    const float cm = (1.0f - cf) * mean;
    const float hk_r = hf;
    const float hk_g = hf + (2.0f / 3.0f);
    const float hk_b = hf + (1.0f / 3.0f);

    #pragma unroll
    for (int k = 0; k < 8; k++) {
        float r  = clip01(R.v[k]  * bf);
        float g  = clip01(G.v[k]  * bf);
        float bl = clip01(Bv.v[k] * bf);
        r  = clip01(fmaf(cf, r,  cm));
        g  = clip01(fmaf(cf, g,  cm));
        bl = clip01(fmaf(cf, bl, cm));
        float gray = 0.299f * r + 0.587f * g + 0.114f * bl;
        float sm = (1.0f - sf) * gray;
        r  = clip01(fmaf(sf, r,  sm));
        g  = clip01(fmaf(sf, g,  sm));
        bl = clip01(fmaf(sf, bl, sm));

        float maxc = fmaxf(r, fmaxf(g, bl));
        float minc = fminf(r, fminf(g, bl));
        float cr   = maxc - minc;
        float crd  = (cr == 0.0f) ? 1.0f : cr;
        float inv6 = rcp_approx(crd) * (1.0f / 6.0f);

        bool pr = (maxc == r);
        bool pg = (maxc == g) && !pr;
        float da   = pr ? g  : (pg ? bl : r);
        float db   = pr ? bl : (pg ? r  : g);
        float off6 = pr ? 0.0f : (pg ? (2.0f / 6.0f) : (4.0f / 6.0f));
        float hbase = fmaf(da - db, inv6, off6);

        R.v[k]  = hsv_ch(hbase + hk_r, cr, minc);
        G.v[k]  = hsv_ch(hbase + hk_g, cr, minc);
        Bv.v[k] = hsv_ch(hbase + hk_b, cr, minc);
    }

    st8_cs(obase,          R.v);
    st8_cs(obase + HW,     G.v);
    st8_cs(obase + 2 * HW, Bv.v);
}

extern "C" void kernel_launch(void* const* d_in, const int* in_sizes, int n_in,
                              void* d_out, int out_size) {
    const float* x  = (const float*)d_in[0];
    const float* bf = (const float*)d_in[1];
    const float* cf = (const float*)d_in[2];
    const float* sf = (const float*)d_in[3];
    const float* hf = (const float*)d_in[4];
    float* out = (float*)d_out;

    // Fresh stream + events every call: no static guards, identical work each
    // call, host-side resources only (no device allocations).  During timed
    // graph replay none of this host code runs — only the captured nodes.
    cudaStream_t s1;
    cudaStreamCreateWithFlags(&s1, cudaStreamNonBlocking);
    cudaEvent_t evR[NGRP], evT[NGRP], evJoin;
    for (int g = 0; g < NGRP; g++) {
        cudaEventCreateWithFlags(&evR[g], cudaEventDisableTiming);
        cudaEventCreateWithFlags(&evT[g], cudaEventDisableTiming);
    }
    cudaEventCreateWithFlags(&evJoin, cudaEventDisableTiming);

    // Pipelined schedule: stream0 = reduce chain, s1 = transform chain.
    //   T(g) waits R(g);  R(g) throttled behind T(g-3) (L2 window <= 3 groups).
    for (int g = 0; g < NGRP; g++) {
        if (g >= 3) cudaStreamWaitEvent(0, evT[g - 3], 0);
        gray_reduce_g<<<dim3(PBLK, IMG_PER_G), TPB, 0, 0>>>(x, bf, g * IMG_PER_G);
        cudaEventRecord(evR[g], 0);

        cudaStreamWaitEvent(s1, evR[g], 0);
        color_xform_g<<<PBLK * IMG_PER_G, TPB, 0, s1>>>(x, bf, cf, sf, hf, out,
                                                        g * IMG_PER_G);
        cudaEventRecord(evT[g], s1);
    }
    cudaEventRecord(evJoin, s1);
    cudaStreamWaitEvent(0, evJoin, 0);
    // Streams/events intentionally not destroyed (destroy during capture would
    // invalidate it; a handful of host-side handles over 2-3 calls is benign).
}